// round 9
// baseline (speedup 1.0000x reference)
#include <cuda_runtime.h>

#define NT 2
#define NPER 256
#define FIT_IN 1600
#define FH 240
#define BB 4
#define NROWS 2048
#define NKNOT 8193          // knots; interp rows 0..8191
#define NROWT 8192
#define SMIN (-8.f)
#define INVH 512.f

__device__ __align__(16) float g_DR[(size_t)NROWS * FIT_IN];
// interleaved table: [e][k][g] -> float2 {G_k[g], G_{k+1}[g]}
__device__ __align__(16) float g_tab[(size_t)4 * NROWT * 100 * 2];

__device__ __forceinline__ float tanhe(float x) {
    float xa = fminf(fmaxf(x, -15.f), 15.f);
    float t = __expf(2.f * xa);
    return __fdividef(t - 1.f, t + 1.f);
}
__device__ __forceinline__ unsigned smaddr(const void* p) {
    unsigned a;
    asm("{.reg .u64 t; cvta.to.shared.u64 t, %1; cvt.u32.u64 %0, t;}" : "=r"(a) : "l"(p));
    return a;
}
__device__ __forceinline__ void cp16(unsigned dst, const void* src) {
    asm volatile("cp.async.ca.shared.global [%0], [%1], 16;" :: "r"(dst), "l"(src));
}
__device__ __forceinline__ void cp_commit() {
    asm volatile("cp.async.commit_group;" ::: "memory");
}

// ============ Kernel 0: tabulate G(s); 64 knots x 4 g-quarters per block ====
#define TW0 0
#define TB0 28
#define TW1 56      // [25][50]
#define TB1 1308
#define TW2 1360    // [50][104]
#define TB2 6560
#define T_SMEM 6660

__global__ void __launch_bounds__(256) build_table_kernel(
    const float* __restrict__ eW0, const float* __restrict__ eB0,
    const float* __restrict__ eW1, const float* __restrict__ eB1,
    const float* __restrict__ eW2, const float* __restrict__ eB2)
{
    extern __shared__ float sm[];
    const int t = threadIdx.x;
    const int e = blockIdx.y;
    if (t < 25) { sm[TW0 + t] = eW0[e * 25 + t]; sm[TB0 + t] = eB0[e * 25 + t]; }
    for (int x = t; x < 1250; x += 256) sm[TW1 + x] = eW1[e * 1250 + x];
    if (t < 50) sm[TB1 + t] = eB1[e * 50 + t];
    for (int x = t; x < 5000; x += 256) { int k = x / 100, g = x - 100 * k; sm[TW2 + k * 104 + g] = eW2[e * 5000 + x]; }
    if (t < 100) sm[TB2 + t] = eB2[e * 100 + t];
    __syncthreads();

    const int kq = t >> 2;            // knot within block (0..63)
    const int q  = t & 3;             // g-quarter (0..3)
    const int idx = blockIdx.x * 64 + kq;
    if (idx >= NKNOT) return;
    const float s = SMIN + (float)idx * (1.f / INVH);

    float h0[25];
#pragma unroll
    for (int k = 0; k < 25; ++k)
        h0[k] = tanhe(fmaf(s, sm[TW0 + k], sm[TB0 + k]));

    float h1[50];
#pragma unroll
    for (int gp = 0; gp < 25; ++gp) {
        float a0 = sm[TB1 + 2 * gp], a1 = sm[TB1 + 2 * gp + 1];
#pragma unroll
        for (int k = 0; k < 25; ++k) {
            float2 w = *(const float2*)&sm[TW1 + k * 50 + 2 * gp];
            a0 = fmaf(h0[k], w.x, a0);
            a1 = fmaf(h0[k], w.y, a1);
        }
        int q0 = 2 * gp;     if (q0 >= 25) q0 -= 25;
        int q1 = 2 * gp + 1; if (q1 >= 25) q1 -= 25;
        h1[2 * gp]     = tanhe(a0) + h0[q0];
        h1[2 * gp + 1] = tanhe(a1) + h0[q1];
    }

    // this thread's g range: [25q, 25q+25) — never crosses the g=50 boundary,
    // so the h2 residual index offset is uniform: -50 iff q >= 2.
    // For float2 alignment, pairs must start at EVEN g:
    //   q even (gbase even): 12 pairs from gbase, scalar tail at gbase+24
    //   q odd  (gbase odd):  scalar head at gbase, 12 pairs from gbase+1
    const int gbase = 25 * q;
    const int roff  = (q >= 2) ? 50 : 0;
    const int podd  = q & 1;
    const int pstart = gbase + podd;            // even
    const int gscal  = podd ? gbase : gbase + 24;
    float* tabe = g_tab + (size_t)e * NROWT * 200;
    const bool wlo = (idx < NROWT);
    const bool whi = (idx > 0);

    // 12 aligned pairs
#pragma unroll 1
    for (int pp = 0; pp < 12; ++pp) {
        const int g = pstart + 2 * pp;
        float a0 = sm[TB2 + g], a1 = sm[TB2 + g + 1];
#pragma unroll
        for (int k = 0; k < 50; ++k) {
            float2 w = *(const float2*)&sm[TW2 + k * 104 + g];
            float hk = h1[k];
            a0 = fmaf(hk, w.x, a0);
            a1 = fmaf(hk, w.y, a1);
        }
        float o0 = tanhe(a0) + h1[g - roff];
        float o1 = tanhe(a1) + h1[g + 1 - roff];
        if (wlo) { tabe[(size_t)idx * 200 + 2 * g] = o0; tabe[(size_t)idx * 200 + 2 * g + 2] = o1; }
        if (whi) { tabe[(size_t)(idx - 1) * 200 + 2 * g + 1] = o0; tabe[(size_t)(idx - 1) * 200 + 2 * g + 3] = o1; }
    }
    // scalar element
    {
        const int g = gscal;
        float a0 = sm[TB2 + g];
#pragma unroll
        for (int k = 0; k < 50; ++k)
            a0 = fmaf(h1[k], sm[TW2 + k * 104 + g], a0);
        float o0 = tanhe(a0) + h1[g - roff];
        if (wlo) tabe[(size_t)idx * 200 + 2 * g] = o0;
        if (whi) tabe[(size_t)(idx - 1) * 200 + 2 * g + 1] = o0;
    }
}

// ============ Kernel A: fused table-interp einsum + DR ============
// smem: blk [128][4] floats, kf int2[128], xyz [4][100]
#define SBLK 0
#define SKF  512     // int2 per m: {byte offset km*800, frac bits}
#define SXYZ 768
#define A_SMEM 1168

__global__ void __launch_bounds__(128) emb_dr_kernel(const float* __restrict__ Ri)
{
    extern __shared__ float sm[];
    int2* skf = (int2*)&sm[SKF];
    const int t = threadIdx.x;
    const int blk = blockIdx.x;
    const int n = blk & 255;
    const int b = (blk >> 8) & 3;
    const int i = blk >> 10;

    const float* ri_base = Ri + ((size_t)((b * NT + i) * NPER + n)) * (NT * 128) * 4;

    float acc0 = 0.f, acc1 = 0.f, acc2 = 0.f, acc3 = 0.f;
    const int tofs = 8 * t;

#pragma unroll 1
    for (int j = 0; j < NT; ++j) {
        __syncthreads();  // prior einsum reads done before restage
        float4 rv = *(const float4*)(ri_base + (size_t)(j * 128 + t) * 4);
        *(float4*)&sm[SBLK + 4 * t] = rv;
        float u = fminf(fmaxf((rv.x - SMIN) * INVH, 0.f), 8191.0f);
        int kk = (int)u;
        skf[t] = make_int2(kk * 800, __float_as_int(u - (float)kk));
        __syncthreads();

        if (t < 100) {
            const char* tb = (const char*)(g_tab + (size_t)(i * NT + j) * NROWT * 200) + tofs;
#pragma unroll 8
            for (int m = 0; m < 128; ++m) {
                const int2 kf = skf[m];
                const float fm = __int_as_float(kf.y);
                float2 v = *(const float2*)(tb + kf.x);
                float gv = fmaf(fm, v.y - v.x, v.x);
                float4 bv = *(const float4*)&sm[SBLK + 4 * m];
                acc0 = fmaf(bv.x, gv, acc0);
                acc1 = fmaf(bv.y, gv, acc1);
                acc2 = fmaf(bv.z, gv, acc2);
                acc3 = fmaf(bv.w, gv, acc3);
            }
        }
    }

    if (t < 100) {
        const float invn = 1.f / 256.f;
        sm[SXYZ + 0 * 100 + t] = acc0 * invn;
        sm[SXYZ + 1 * 100 + t] = acc1 * invn;
        sm[SXYZ + 2 * 100 + t] = acc2 * invn;
        sm[SXYZ + 3 * 100 + t] = acc3 * invn;
    }
    __syncthreads();

    const int row = (i * BB + b) * NPER + n;
    float* drow = g_DR + (size_t)row * FIT_IN;
#pragma unroll 1
    for (int o = 0; o < 13; ++o) {
        int idx = t + o * 128;
        if (idx < FIT_IN) {
            int g = idx >> 4, h = idx & 15;
            float a = sm[SXYZ + 0 * 100 + g] * sm[SXYZ + 0 * 100 + h];
            a = fmaf(sm[SXYZ + 1 * 100 + g], sm[SXYZ + 1 * 100 + h], a);
            a = fmaf(sm[SXYZ + 2 * 100 + g], sm[SXYZ + 2 * 100 + h], a);
            a = fmaf(sm[SXYZ + 3 * 100 + g], sm[SXYZ + 3 * 100 + h], a);
            drow[idx] = a;
        }
    }
}

// ============ Kernel B: fit net, 8-row tiles, 2 blocks/SM ============
#define KT 16
#define SM_DR   0
#define SM_WS   12800
#define SM_ACTA 20480
#define SM_ACTB 22400
#define B_SMEM  24320

#define ROWF2(r, D, WV) \
    acc[r][0] = fmaf(D, WV.x, acc[r][0]); acc[r][1] = fmaf(D, WV.y, acc[r][1]); \
    acc[r][2] = fmaf(D, WV.z, acc[r][2]); acc[r][3] = fmaf(D, WV.w, acc[r][3]);
#define STEP2(WV, D0, D1) ROWF2(0, D0, WV) ROWF2(1, D1, WV)

__device__ __forceinline__ void run_layer8(
    const float* __restrict__ Wg, const float* __restrict__ bg, int K,
    const float* __restrict__ dpan, int dstride,
    float* w_s, const float* __restrict__ res, float* __restrict__ outp,
    int tid, int ry, int c0)
{
    float acc[2][4];
    {
        float4 bv = *(const float4*)&bg[c0];
        acc[0][0] = bv.x; acc[0][1] = bv.y; acc[0][2] = bv.z; acc[0][3] = bv.w;
        acc[1][0] = bv.x; acc[1][1] = bv.y; acc[1][2] = bv.z; acc[1][3] = bv.w;
    }
    const int T = K / KT;

    for (int x = tid; x < KT * 60; x += 256) {
        int kk = x / 60, seg = x - kk * 60;
        cp16(smaddr(w_s + kk * FH + seg * 4), Wg + (size_t)kk * FH + seg * 4);
    }
    cp_commit();

#pragma unroll 1
    for (int t = 0; t < T; ++t) {
        if (t + 1 < T) {
            float* wnext = w_s + ((t + 1) & 1) * (KT * FH);
            const float* wgn = Wg + (size_t)(t + 1) * KT * FH;
            for (int x = tid; x < KT * 60; x += 256) {
                int kk = x / 60, seg = x - kk * 60;
                cp16(smaddr(wnext + kk * FH + seg * 4), wgn + (size_t)kk * FH + seg * 4);
            }
            cp_commit();
            asm volatile("cp.async.wait_group 1;" ::: "memory");
        } else {
            asm volatile("cp.async.wait_group 0;" ::: "memory");
        }
        __syncthreads();

        const float* wt = w_s + (t & 1) * (KT * FH);
        const float* dp = dpan + (size_t)(2 * ry) * dstride + t * KT;
#pragma unroll
        for (int k4 = 0; k4 < KT; k4 += 4) {
            float4 d0 = *(const float4*)(dp + k4);
            float4 d1 = *(const float4*)(dp + dstride + k4);
            float4 wv0 = *(const float4*)(wt + (k4 + 0) * FH + c0);
            float4 wv1 = *(const float4*)(wt + (k4 + 1) * FH + c0);
            float4 wv2 = *(const float4*)(wt + (k4 + 2) * FH + c0);
            float4 wv3 = *(const float4*)(wt + (k4 + 3) * FH + c0);
            STEP2(wv0, d0.x, d1.x)
            STEP2(wv1, d0.y, d1.y)
            STEP2(wv2, d0.z, d1.z)
            STEP2(wv3, d0.w, d1.w)
        }
        __syncthreads();
    }

#pragma unroll
    for (int r = 0; r < 2; ++r) {
        int row = 2 * ry + r;
        float4 o;
        o.x = tanhe(acc[r][0]); o.y = tanhe(acc[r][1]);
        o.z = tanhe(acc[r][2]); o.w = tanhe(acc[r][3]);
        if (res) {
            float4 rv = *(const float4*)&res[row * FH + c0];
            o.x += rv.x; o.y += rv.y; o.z += rv.z; o.w += rv.w;
        }
        *(float4*)&outp[row * FH + c0] = o;
    }
}

__global__ void __launch_bounds__(256, 2) fit_kernel(
    const float* __restrict__ W0, const float* __restrict__ b0,
    const float* __restrict__ W1, const float* __restrict__ b1,
    const float* __restrict__ W2, const float* __restrict__ b2,
    const float* __restrict__ W3, const float* __restrict__ b3,
    float* __restrict__ out)
{
    extern __shared__ float sm[];
    float* dr   = sm + SM_DR;
    float* w_s  = sm + SM_WS;
    float* actA = sm + SM_ACTA;
    float* actB = sm + SM_ACTB;

    const int tid = threadIdx.x;
    const int i = blockIdx.x >> 7;
    const int r0 = (blockIdx.x & 127) * 8;
    const int ry = tid >> 6;
    const int cx = tid & 63;
    const int cc = (cx < 60) ? cx : 59;
    const int c0 = cc * 4;

    const float* W0g = W0 + (size_t)i * FIT_IN * FH;
    const float* W1g = W1 + (size_t)i * FH * FH;
    const float* W2g = W2 + (size_t)i * FH * FH;
    const float* W3g = W3 + (size_t)i * FH;
    const float* b0g = b0 + i * FH;
    const float* b1g = b1 + i * FH;
    const float* b2g = b2 + i * FH;
    const float  b3v = b3[i];

    {
        const float* drg = g_DR + (size_t)(i * (BB * NPER) + r0) * FIT_IN;
        for (int x = tid; x < (8 * FIT_IN) / 4; x += 256)
            cp16(smaddr(dr + 4 * x), drg + 4 * x);
        cp_commit();
    }

    run_layer8(W0g, b0g, FIT_IN, dr, FIT_IN, w_s, nullptr, actA, tid, ry, c0);
    __syncthreads();
    run_layer8(W1g, b1g, FH, actA, FH, w_s, actA, actB, tid, ry, c0);
    __syncthreads();
    run_layer8(W2g, b2g, FH, actB, FH, w_s, actB, actA, tid, ry, c0);
    __syncthreads();

    const int wi = tid >> 5, lane = tid & 31;
    float p = 0.f;
    for (int o2 = lane; o2 < FH; o2 += 32) p = fmaf(actA[wi * FH + o2], W3g[o2], p);
#pragma unroll
    for (int sd = 16; sd > 0; sd >>= 1) p += __shfl_down_sync(0xffffffffu, p, sd);
    if (lane == 0) {
        int rowg = r0 + wi;
        int bb = rowg >> 8, nn = rowg & 255;
        out[(bb * NT + i) * NPER + nn] = p + b3v;
    }
}

// ---------------- launch ----------------
extern "C" void kernel_launch(void* const* d_in, const int* in_sizes, int n_in,
                              void* d_out, int out_size) {
    const float* Ri  = (const float*)d_in[0];
    const float* eW0 = (const float*)d_in[1];
    const float* eB0 = (const float*)d_in[2];
    const float* eW1 = (const float*)d_in[3];
    const float* eB1 = (const float*)d_in[4];
    const float* eW2 = (const float*)d_in[5];
    const float* eB2 = (const float*)d_in[6];
    const float* fW0 = (const float*)d_in[7];
    const float* fB0 = (const float*)d_in[8];
    const float* fW1 = (const float*)d_in[9];
    const float* fB1 = (const float*)d_in[10];
    const float* fW2 = (const float*)d_in[11];
    const float* fB2 = (const float*)d_in[12];
    const float* fW3 = (const float*)d_in[13];
    const float* fB3 = (const float*)d_in[14];
    float* out = (float*)d_out;

    cudaFuncSetAttribute(build_table_kernel, cudaFuncAttributeMaxDynamicSharedMemorySize,
                         T_SMEM * 4);
    cudaFuncSetAttribute(emb_dr_kernel, cudaFuncAttributeMaxDynamicSharedMemorySize,
                         A_SMEM * 4);
    cudaFuncSetAttribute(fit_kernel, cudaFuncAttributeMaxDynamicSharedMemorySize,
                         B_SMEM * 4);

    build_table_kernel<<<dim3(129, 4), 256, T_SMEM * 4>>>(eW0, eB0, eW1, eB1, eW2, eB2);
    emb_dr_kernel<<<NROWS, 128, A_SMEM * 4>>>(Ri);
    fit_kernel<<<256, 256, B_SMEM * 4>>>(fW0, fB0, fW1, fB1, fW2, fB2, fW3, fB3, out);
}

// round 10
// speedup vs baseline: 1.9650x; 1.9650x over previous
#include <cuda_runtime.h>

#define NT 2
#define NPER 256
#define FIT_IN 1600
#define FH 240
#define BB 4
#define NROWS 2048
#define NKNOT 2049          // knots; interp rows 0..2047
#define NROWT 2048
#define SMIN (-8.f)
#define INVH 128.f

__device__ __align__(16) float g_DR[(size_t)NROWS * FIT_IN];
// interleaved table: [e][k][g] -> float2 {G_k[g], G_{k+1}[g]}
__device__ __align__(16) float g_tab[(size_t)4 * NROWT * 100 * 2];

__device__ __forceinline__ float tanhe(float x) {
    float xa = fminf(fmaxf(x, -15.f), 15.f);
    float t = __expf(2.f * xa);
    return __fdividef(t - 1.f, t + 1.f);
}
__device__ __forceinline__ unsigned smaddr(const void* p) {
    unsigned a;
    asm("{.reg .u64 t; cvta.to.shared.u64 t, %1; cvt.u32.u64 %0, t;}" : "=r"(a) : "l"(p));
    return a;
}
__device__ __forceinline__ void cp16(unsigned dst, const void* src) {
    asm volatile("cp.async.ca.shared.global [%0], [%1], 16;" :: "r"(dst), "l"(src));
}
__device__ __forceinline__ void cp_commit() {
    asm volatile("cp.async.commit_group;" ::: "memory");
}

// ============ Kernel 0: tabulate G(s); 64 knots x 4 g-quarters per block ====
#define TW0 0
#define TB0 28
#define TW1 56      // [25][50]
#define TB1 1308
#define TW2 1360    // [50][104]
#define TB2 6560
#define T_SMEM 6660

__global__ void __launch_bounds__(256) build_table_kernel(
    const float* __restrict__ eW0, const float* __restrict__ eB0,
    const float* __restrict__ eW1, const float* __restrict__ eB1,
    const float* __restrict__ eW2, const float* __restrict__ eB2)
{
    extern __shared__ float sm[];
    const int t = threadIdx.x;
    const int e = blockIdx.y;
    if (t < 25) { sm[TW0 + t] = eW0[e * 25 + t]; sm[TB0 + t] = eB0[e * 25 + t]; }
    for (int x = t; x < 1250; x += 256) sm[TW1 + x] = eW1[e * 1250 + x];
    if (t < 50) sm[TB1 + t] = eB1[e * 50 + t];
    for (int x = t; x < 5000; x += 256) { int k = x / 100, g = x - 100 * k; sm[TW2 + k * 104 + g] = eW2[e * 5000 + x]; }
    if (t < 100) sm[TB2 + t] = eB2[e * 100 + t];
    __syncthreads();

    const int kq = t >> 2;            // knot within block (0..63)
    const int q  = t & 3;             // g-quarter (0..3)
    const int idx = blockIdx.x * 64 + kq;
    if (idx >= NKNOT) return;
    const float s = SMIN + (float)idx * (1.f / INVH);

    float h0[25];
#pragma unroll
    for (int k = 0; k < 25; ++k)
        h0[k] = tanhe(fmaf(s, sm[TW0 + k], sm[TB0 + k]));

    float h1[50];
#pragma unroll
    for (int gp = 0; gp < 25; ++gp) {
        float a0 = sm[TB1 + 2 * gp], a1 = sm[TB1 + 2 * gp + 1];
#pragma unroll
        for (int k = 0; k < 25; ++k) {
            float2 w = *(const float2*)&sm[TW1 + k * 50 + 2 * gp];
            a0 = fmaf(h0[k], w.x, a0);
            a1 = fmaf(h0[k], w.y, a1);
        }
        int q0 = 2 * gp;     if (q0 >= 25) q0 -= 25;
        int q1 = 2 * gp + 1; if (q1 >= 25) q1 -= 25;
        h1[2 * gp]     = tanhe(a0) + h0[q0];
        h1[2 * gp + 1] = tanhe(a1) + h0[q1];
    }

    // g range [25q, 25q+25) never crosses g=50, so residual offset is uniform.
    // float2 alignment: pairs must start at EVEN g.
    const int gbase = 25 * q;
    const int roff  = (q >= 2) ? 50 : 0;
    const int podd  = q & 1;
    const int pstart = gbase + podd;            // even
    const int gscal  = podd ? gbase : gbase + 24;
    float* tabe = g_tab + (size_t)e * NROWT * 200;
    const bool wlo = (idx < NROWT);
    const bool whi = (idx > 0);

#pragma unroll 1
    for (int pp = 0; pp < 12; ++pp) {
        const int g = pstart + 2 * pp;
        float a0 = sm[TB2 + g], a1 = sm[TB2 + g + 1];
#pragma unroll
        for (int k = 0; k < 50; ++k) {
            float2 w = *(const float2*)&sm[TW2 + k * 104 + g];
            float hk = h1[k];
            a0 = fmaf(hk, w.x, a0);
            a1 = fmaf(hk, w.y, a1);
        }
        float o0 = tanhe(a0) + h1[g - roff];
        float o1 = tanhe(a1) + h1[g + 1 - roff];
        if (wlo) { tabe[(size_t)idx * 200 + 2 * g] = o0; tabe[(size_t)idx * 200 + 2 * g + 2] = o1; }
        if (whi) { tabe[(size_t)(idx - 1) * 200 + 2 * g + 1] = o0; tabe[(size_t)(idx - 1) * 200 + 2 * g + 3] = o1; }
    }
    {
        const int g = gscal;
        float a0 = sm[TB2 + g];
#pragma unroll
        for (int k = 0; k < 50; ++k)
            a0 = fmaf(h1[k], sm[TW2 + k * 104 + g], a0);
        float o0 = tanhe(a0) + h1[g - roff];
        if (wlo) tabe[(size_t)idx * 200 + 2 * g] = o0;
        if (whi) tabe[(size_t)(idx - 1) * 200 + 2 * g + 1] = o0;
    }
}

// ============ Kernel A: fused table-interp einsum + DR (R7-proven form) =====
// smem: blk [128][4], k[128](int), f[128], xyz [4][100]
#define SBLK 0
#define SKI  512
#define SFR  640
#define SXYZ 768
#define A_SMEM 1168

__global__ void __launch_bounds__(128) emb_dr_kernel(const float* __restrict__ Ri)
{
    extern __shared__ float sm[];
    int* smi = (int*)sm;
    const int t = threadIdx.x;
    const int blk = blockIdx.x;
    const int n = blk & 255;
    const int b = (blk >> 8) & 3;
    const int i = blk >> 10;

    const float* ri_base = Ri + ((size_t)((b * NT + i) * NPER + n)) * (NT * 128) * 4;

    float acc0 = 0.f, acc1 = 0.f, acc2 = 0.f, acc3 = 0.f;

#pragma unroll 1
    for (int j = 0; j < NT; ++j) {
        __syncthreads();  // prior einsum reads done before restage
        float4 rv = *(const float4*)(ri_base + (size_t)(j * 128 + t) * 4);
        *(float4*)&sm[SBLK + 4 * t] = rv;
        float u = fminf(fmaxf((rv.x - SMIN) * INVH, 0.f), 2047.0f);
        int kk = (int)u;
        smi[SKI + t] = kk;
        sm[SFR + t] = u - (float)kk;
        __syncthreads();

        if (t < 100) {
            const float* tabe = g_tab + (size_t)(i * NT + j) * NROWT * 200;
#pragma unroll 4
            for (int m = 0; m < 128; ++m) {
                const int km = smi[SKI + m];
                const float fm = sm[SFR + m];
                float2 v = *(const float2*)(tabe + (size_t)km * 200 + 2 * t);
                float gv = fmaf(fm, v.y - v.x, v.x);
                float4 bv = *(const float4*)&sm[SBLK + 4 * m];
                acc0 = fmaf(bv.x, gv, acc0);
                acc1 = fmaf(bv.y, gv, acc1);
                acc2 = fmaf(bv.z, gv, acc2);
                acc3 = fmaf(bv.w, gv, acc3);
            }
        }
    }

    if (t < 100) {
        const float invn = 1.f / 256.f;
        sm[SXYZ + 0 * 100 + t] = acc0 * invn;
        sm[SXYZ + 1 * 100 + t] = acc1 * invn;
        sm[SXYZ + 2 * 100 + t] = acc2 * invn;
        sm[SXYZ + 3 * 100 + t] = acc3 * invn;
    }
    __syncthreads();

    const int row = (i * BB + b) * NPER + n;
    float* drow = g_DR + (size_t)row * FIT_IN;
#pragma unroll 1
    for (int o = 0; o < 13; ++o) {
        int idx = t + o * 128;
        if (idx < FIT_IN) {
            int g = idx >> 4, h = idx & 15;
            float a = sm[SXYZ + 0 * 100 + g] * sm[SXYZ + 0 * 100 + h];
            a = fmaf(sm[SXYZ + 1 * 100 + g], sm[SXYZ + 1 * 100 + h], a);
            a = fmaf(sm[SXYZ + 2 * 100 + g], sm[SXYZ + 2 * 100 + h], a);
            a = fmaf(sm[SXYZ + 3 * 100 + g], sm[SXYZ + 3 * 100 + h], a);
            drow[idx] = a;
        }
    }
}

// ============ Kernel B: fit net, 8-row tiles, 2 blocks/SM ============
#define KT 16
#define SM_DR   0
#define SM_WS   12800
#define SM_ACTA 20480
#define SM_ACTB 22400
#define B_SMEM  24320

#define ROWF2(r, D, WV) \
    acc[r][0] = fmaf(D, WV.x, acc[r][0]); acc[r][1] = fmaf(D, WV.y, acc[r][1]); \
    acc[r][2] = fmaf(D, WV.z, acc[r][2]); acc[r][3] = fmaf(D, WV.w, acc[r][3]);
#define STEP2(WV, D0, D1) ROWF2(0, D0, WV) ROWF2(1, D1, WV)

__device__ __forceinline__ void run_layer8(
    const float* __restrict__ Wg, const float* __restrict__ bg, int K,
    const float* __restrict__ dpan, int dstride,
    float* w_s, const float* __restrict__ res, float* __restrict__ outp,
    int tid, int ry, int c0)
{
    float acc[2][4];
    {
        float4 bv = *(const float4*)&bg[c0];
        acc[0][0] = bv.x; acc[0][1] = bv.y; acc[0][2] = bv.z; acc[0][3] = bv.w;
        acc[1][0] = bv.x; acc[1][1] = bv.y; acc[1][2] = bv.z; acc[1][3] = bv.w;
    }
    const int T = K / KT;

    for (int x = tid; x < KT * 60; x += 256) {
        int kk = x / 60, seg = x - kk * 60;
        cp16(smaddr(w_s + kk * FH + seg * 4), Wg + (size_t)kk * FH + seg * 4);
    }
    cp_commit();

#pragma unroll 1
    for (int t = 0; t < T; ++t) {
        if (t + 1 < T) {
            float* wnext = w_s + ((t + 1) & 1) * (KT * FH);
            const float* wgn = Wg + (size_t)(t + 1) * KT * FH;
            for (int x = tid; x < KT * 60; x += 256) {
                int kk = x / 60, seg = x - kk * 60;
                cp16(smaddr(wnext + kk * FH + seg * 4), wgn + (size_t)kk * FH + seg * 4);
            }
            cp_commit();
            asm volatile("cp.async.wait_group 1;" ::: "memory");
        } else {
            asm volatile("cp.async.wait_group 0;" ::: "memory");
        }
        __syncthreads();

        const float* wt = w_s + (t & 1) * (KT * FH);
        const float* dp = dpan + (size_t)(2 * ry) * dstride + t * KT;
#pragma unroll
        for (int k4 = 0; k4 < KT; k4 += 4) {
            float4 d0 = *(const float4*)(dp + k4);
            float4 d1 = *(const float4*)(dp + dstride + k4);
            float4 wv0 = *(const float4*)(wt + (k4 + 0) * FH + c0);
            float4 wv1 = *(const float4*)(wt + (k4 + 1) * FH + c0);
            float4 wv2 = *(const float4*)(wt + (k4 + 2) * FH + c0);
            float4 wv3 = *(const float4*)(wt + (k4 + 3) * FH + c0);
            STEP2(wv0, d0.x, d1.x)
            STEP2(wv1, d0.y, d1.y)
            STEP2(wv2, d0.z, d1.z)
            STEP2(wv3, d0.w, d1.w)
        }
        __syncthreads();
    }

#pragma unroll
    for (int r = 0; r < 2; ++r) {
        int row = 2 * ry + r;
        float4 o;
        o.x = tanhe(acc[r][0]); o.y = tanhe(acc[r][1]);
        o.z = tanhe(acc[r][2]); o.w = tanhe(acc[r][3]);
        if (res) {
            float4 rv = *(const float4*)&res[row * FH + c0];
            o.x += rv.x; o.y += rv.y; o.z += rv.z; o.w += rv.w;
        }
        *(float4*)&outp[row * FH + c0] = o;
    }
}

__global__ void __launch_bounds__(256, 2) fit_kernel(
    const float* __restrict__ W0, const float* __restrict__ b0,
    const float* __restrict__ W1, const float* __restrict__ b1,
    const float* __restrict__ W2, const float* __restrict__ b2,
    const float* __restrict__ W3, const float* __restrict__ b3,
    float* __restrict__ out)
{
    extern __shared__ float sm[];
    float* dr   = sm + SM_DR;
    float* w_s  = sm + SM_WS;
    float* actA = sm + SM_ACTA;
    float* actB = sm + SM_ACTB;

    const int tid = threadIdx.x;
    const int i = blockIdx.x >> 7;
    const int r0 = (blockIdx.x & 127) * 8;
    const int ry = tid >> 6;
    const int cx = tid & 63;
    const int cc = (cx < 60) ? cx : 59;
    const int c0 = cc * 4;

    const float* W0g = W0 + (size_t)i * FIT_IN * FH;
    const float* W1g = W1 + (size_t)i * FH * FH;
    const float* W2g = W2 + (size_t)i * FH * FH;
    const float* W3g = W3 + (size_t)i * FH;
    const float* b0g = b0 + i * FH;
    const float* b1g = b1 + i * FH;
    const float* b2g = b2 + i * FH;
    const float  b3v = b3[i];

    {
        const float* drg = g_DR + (size_t)(i * (BB * NPER) + r0) * FIT_IN;
        for (int x = tid; x < (8 * FIT_IN) / 4; x += 256)
            cp16(smaddr(dr + 4 * x), drg + 4 * x);
        cp_commit();
    }

    run_layer8(W0g, b0g, FIT_IN, dr, FIT_IN, w_s, nullptr, actA, tid, ry, c0);
    __syncthreads();
    run_layer8(W1g, b1g, FH, actA, FH, w_s, actA, actB, tid, ry, c0);
    __syncthreads();
    run_layer8(W2g, b2g, FH, actB, FH, w_s, actB, actA, tid, ry, c0);
    __syncthreads();

    const int wi = tid >> 5, lane = tid & 31;
    float p = 0.f;
    for (int o2 = lane; o2 < FH; o2 += 32) p = fmaf(actA[wi * FH + o2], W3g[o2], p);
#pragma unroll
    for (int sd = 16; sd > 0; sd >>= 1) p += __shfl_down_sync(0xffffffffu, p, sd);
    if (lane == 0) {
        int rowg = r0 + wi;
        int bb = rowg >> 8, nn = rowg & 255;
        out[(bb * NT + i) * NPER + nn] = p + b3v;
    }
}

// ---------------- launch ----------------
extern "C" void kernel_launch(void* const* d_in, const int* in_sizes, int n_in,
                              void* d_out, int out_size) {
    const float* Ri  = (const float*)d_in[0];
    const float* eW0 = (const float*)d_in[1];
    const float* eB0 = (const float*)d_in[2];
    const float* eW1 = (const float*)d_in[3];
    const float* eB1 = (const float*)d_in[4];
    const float* eW2 = (const float*)d_in[5];
    const float* eB2 = (const float*)d_in[6];
    const float* fW0 = (const float*)d_in[7];
    const float* fB0 = (const float*)d_in[8];
    const float* fW1 = (const float*)d_in[9];
    const float* fB1 = (const float*)d_in[10];
    const float* fW2 = (const float*)d_in[11];
    const float* fB2 = (const float*)d_in[12];
    const float* fW3 = (const float*)d_in[13];
    const float* fB3 = (const float*)d_in[14];
    float* out = (float*)d_out;

    cudaFuncSetAttribute(build_table_kernel, cudaFuncAttributeMaxDynamicSharedMemorySize,
                         T_SMEM * 4);
    cudaFuncSetAttribute(emb_dr_kernel, cudaFuncAttributeMaxDynamicSharedMemorySize,
                         A_SMEM * 4);
    cudaFuncSetAttribute(fit_kernel, cudaFuncAttributeMaxDynamicSharedMemorySize,
                         B_SMEM * 4);

    build_table_kernel<<<dim3(33, 4), 256, T_SMEM * 4>>>(eW0, eB0, eW1, eB1, eW2, eB2);
    emb_dr_kernel<<<NROWS, 128, A_SMEM * 4>>>(Ri);
    fit_kernel<<<256, 256, B_SMEM * 4>>>(fW0, fB0, fW1, fB1, fW2, fB2, fW3, fB3, out);
}